// round 11
// baseline (speedup 1.0000x reference)
#include <cuda_runtime.h>
#include <cuda_bf16.h>
#include <cstdint>

#define BB      4
#define IN_DIM  8
#define OUT_DIM 64
#define N_WIN   64
#define N_SEQ   4096
#define N_REAL  6144

#define T_TILE  64
#define NTILES  (N_REAL / T_TILE)   // 96
#define THREADS 256

// Precomputed B fragment table (validated in R8): per (i, nb) 512 uint4 =
// [kc:4][slot:4][lane:32], slots = {bh0-3, bh4-7, bl0-3, bl4-7}. 128KB.
__device__ __align__(16) uint32_t g_Bf[IN_DIM * 2 * 4 * 512];

// ---------------- helpers ----------------

// pack {lo16: bf16(z0), hi16: bf16(z1)}
__device__ __forceinline__ uint32_t bfpair(float z0, float z1) {
    uint32_t r;
    asm("cvt.rn.bf16x2.f32 %0, %1, %2;" : "=r"(r) : "f"(z1), "f"(z0));
    return r;
}

__device__ __forceinline__ void mma_bf16(float* d, const uint32_t* a, uint32_t b0, uint32_t b1) {
    asm volatile(
        "mma.sync.aligned.m16n8k16.row.col.f32.bf16.bf16.f32 "
        "{%0,%1,%2,%3}, {%4,%5,%6,%7}, {%8,%9}, {%0,%1,%2,%3};"
        : "+f"(d[0]), "+f"(d[1]), "+f"(d[2]), "+f"(d[3])
        : "r"(a[0]), "r"(a[1]), "r"(a[2]), "r"(a[3]), "r"(b0), "r"(b1));
}

// ---------------- weight prep (identical to validated R8) ----------------
// B per i: B[k][o] = W[o][i][63-k].  m16n8k16 col-B fragment, n8 group c (f=2c+q):
//   word of lane l = ( B[kk][o], B[kk+1][o] ),  o = 32nb + 8c + l/4, kk = 16kc + 2(l%4) + 8q.

__global__ void wprep_frag(const float* __restrict__ w) {
    int g = blockIdx.x * 256 + threadIdx.x;     // 32768 words
    if (g >= IN_DIM * 2 * 4 * 512) return;
    int lane = g & 31;
    int j    = (g >> 5) & 15;
    int kc   = (g >> 9) & 3;
    int nb   = (g >> 11) & 1;
    int i    = (g >> 12) & 7;
    int f    = j & 7;
    int lopart = j >> 3;
    int c = f >> 1, q = f & 1;
    int o  = 32 * nb + 8 * c + (lane >> 2);
    int kk = 16 * kc + 2 * (lane & 3) + 8 * q;
    float v0 = w[(o * IN_DIM + i) * N_WIN + (63 - kk)];
    float v1 = w[(o * IN_DIM + i) * N_WIN + (62 - kk)];
    __nv_bfloat16 h0 = __float2bfloat16(v0), h1 = __float2bfloat16(v1);
    uint32_t word;
    if (!lopart) word = bfpair(__bfloat162float(h0), __bfloat162float(h1));
    else         word = bfpair(v0 - __bfloat162float(h0), v1 - __bfloat162float(h1));
    int idx = (((i * 2 + nb) * 4 + kc) * 4 + (j >> 2)) * 128 + lane * 4 + (j & 3);
    g_Bf[idx] = word;
}

// ---------------- main kernel ----------------
// SMEM: zpair_hi 8x128 u32 @0 | zpair_lo @4096 | zraw 8x128 f32 @8192 |
//       bias @12288 | outtile 64x68 f32 @12544
#define SM_ZPH  0
#define SM_ZPL  4096
#define SM_ZRAW 8192
#define SM_BIAS 12288
#define SM_OUT  12544
#define PITCHW  68
#define SMEM_TOTAL (SM_OUT + OUT_DIM * PITCHW * 4)   // 29952

__global__ __launch_bounds__(THREADS, 3)
void conv_mma(const float* __restrict__ x, const int* __restrict__ srcIdx,
              const float* __restrict__ bias, float* __restrict__ out) {
    extern __shared__ __align__(16) unsigned char smem[];
    uint32_t* zph_all = (uint32_t*)(smem + SM_ZPH);
    uint32_t* zpl_all = (uint32_t*)(smem + SM_ZPL);
    float*    zraw    = (float*)(smem + SM_ZRAW);
    float*    bias_s  = (float*)(smem + SM_BIAS);
    float*    outtile = (float*)(smem + SM_OUT);

    const int tid  = threadIdx.x;
    const int wid  = tid >> 5;
    const int lane = tid & 31;
    const int b    = blockIdx.x / NTILES;
    const int t0   = (blockIdx.x % NTILES) * T_TILE;

    if (tid < OUT_DIM) bias_s[tid] = bias[tid];
#pragma unroll
    for (int p = 0; p < 4; p++) zraw[tid + p * THREADS] = 0.f;
    __syncthreads();

    // ---- stage z window [t0-63, t0+63] (127 entries) via PARALLEL scan of sourceIdx ----
    {
        const int tlo = t0 - 63;
        const int4* r4 = (const int4*)(srcIdx + b * N_SEQ) + tid * 4;
        const float* xb = x + b * IN_DIM * N_SEQ;
#pragma unroll
        for (int q = 0; q < 4; q++) {
            int4 v = r4[q];
            int s0 = tid * 16 + q * 4;
            int vv[4] = {v.x, v.y, v.z, v.w};
#pragma unroll
            for (int e = 0; e < 4; e++) {
                int tl = vv[e] - tlo;
                if ((unsigned)tl < 127u) {
                    int s = s0 + e;
#pragma unroll
                    for (int i = 0; i < IN_DIM; i++)
                        zraw[i * 128 + tl] = xb[i * N_SEQ + s];
                }
            }
        }
    }
    __syncthreads();

    // ---- build hi/lo pair tables: zpair[i][k] = pack(z[k], z[k+1]) ----
#pragma unroll
    for (int p = 0; p < 4; p++) {
        int e = tid + p * THREADS;                   // 0..1023
        int k = e & 127;                             // stride 128 -> mask exact
        float z0 = zraw[e];
        float z1 = (k < 127) ? zraw[e + 1] : 0.f;
        uint32_t hp = bfpair(z0, z1);
        float h0 = __uint_as_float(hp << 16);
        float h1 = __uint_as_float(hp & 0xffff0000u);
        zph_all[e] = hp;
        zpl_all[e] = bfpair(z0 - h0, z1 - h1);
    }
    __syncthreads();

    // ---- fragment geometry (R8): warp = m16 tile (mb 0..3) x n32 half (nb 0..1) ----
    const int mb  = wid & 3;
    const int nb  = wid >> 2;
    const int lg  = lane >> 2;
    const int lp4 = lane & 3;
    const int rA  = 16 * mb + lg;

    float acc[4][4];
#pragma unroll
    for (int c = 0; c < 4; c++)
#pragma unroll
        for (int q = 0; q < 4; q++) acc[c][q] = 0.f;

    const uint4* bf_base = (const uint4*)g_Bf + nb * 512 + lane;

    // load A words (Hankel: 3 distinct) and B vectors for step s = (i<<2)|kc
    auto loadA = [&](int s, uint32_t* wh, uint32_t* wl) {
        int i = s >> 2, kc = s & 3;
        const uint32_t* zph = zph_all + i * 128 + rA + 16 * kc + 2 * lp4;
        const uint32_t* zpl = zpl_all + i * 128 + rA + 16 * kc + 2 * lp4;
        wh[0] = zph[0]; wh[1] = zph[8]; wh[2] = zph[16];
        wl[0] = zpl[0]; wl[1] = zpl[8]; wl[2] = zpl[16];
    };
    auto loadB = [&](int s, uint4* B) {
        int i = s >> 2, kc = s & 3;
        const uint4* bp = bf_base + i * 1024 + kc * 128;
        B[0] = bp[0]; B[1] = bp[32]; B[2] = bp[64]; B[3] = bp[96];
    };

    // ---- software-pipelined main loop: 32 steps, prefetch distance 1 ----
    uint32_t cwh[3], cwl[3];
    uint4 cB[4];
    loadA(0, cwh, cwl);
    loadB(0, cB);

#pragma unroll 4
    for (int s = 0; s < 32; s++) {
        uint32_t nwh[3], nwl[3];
        uint4 nB[4];
        if (s < 31) { loadB(s + 1, nB); loadA(s + 1, nwh, nwl); }

        uint32_t ah[4] = {cwh[0], cwh[1], cwh[1], cwh[2]};
        uint32_t al[4] = {cwl[0], cwl[1], cwl[1], cwl[2]};
        uint32_t bh[8] = {cB[0].x, cB[0].y, cB[0].z, cB[0].w,
                          cB[1].x, cB[1].y, cB[1].z, cB[1].w};
        uint32_t bl[8] = {cB[2].x, cB[2].y, cB[2].z, cB[2].w,
                          cB[3].x, cB[3].y, cB[3].z, cB[3].w};

#pragma unroll
        for (int c = 0; c < 4; c++) mma_bf16(acc[c], ah, bh[2 * c], bh[2 * c + 1]); // zhi*whi
#pragma unroll
        for (int c = 0; c < 4; c++) mma_bf16(acc[c], ah, bl[2 * c], bl[2 * c + 1]); // zhi*wlo
#pragma unroll
        for (int c = 0; c < 4; c++) mma_bf16(acc[c], al, bh[2 * c], bh[2 * c + 1]); // zlo*whi

        if (s < 31) {
            cwh[0] = nwh[0]; cwh[1] = nwh[1]; cwh[2] = nwh[2];
            cwl[0] = nwl[0]; cwl[1] = nwl[1]; cwl[2] = nwl[2];
            cB[0] = nB[0]; cB[1] = nB[1]; cB[2] = nB[2]; cB[3] = nB[3];
        }
    }

    // ---- epilogue: D[t][o] + bias -> outtile[o][t] (pitch 68) ----
    {
        const int tl0 = rA;
#pragma unroll
        for (int c = 0; c < 4; c++) {
            int o0 = 32 * nb + 8 * c + 2 * lp4;
            outtile[o0 * PITCHW + tl0]           = acc[c][0] + bias_s[o0];
            outtile[(o0 + 1) * PITCHW + tl0]     = acc[c][1] + bias_s[o0 + 1];
            outtile[o0 * PITCHW + tl0 + 8]       = acc[c][2] + bias_s[o0];
            outtile[(o0 + 1) * PITCHW + tl0 + 8] = acc[c][3] + bias_s[o0 + 1];
        }
    }
    __syncthreads();

    // ---- coalesced STG.128: 1024 float4 quads, 4 per thread ----
#pragma unroll
    for (int r2 = 0; r2 < 4; r2++) {
        int u  = tid + r2 * THREADS;                 // 0..1023
        int o  = u >> 4;
        int tq = u & 15;
        float4 v = *(float4*)(outtile + o * PITCHW + 4 * tq);
        *(float4*)(out + (b * OUT_DIM + o) * N_REAL + t0 + 4 * tq) = v;
    }
}

// ---------------- launch ----------------

extern "C" void kernel_launch(void* const* d_in, const int* in_sizes, int n_in,
                              void* d_out, int out_size) {
    const float* x      = (const float*)d_in[0];   // (4, 8, 4096)
    const float* weight = (const float*)d_in[1];   // (64, 8, 64)
    const float* bias   = (const float*)d_in[2];   // (64,)
    const int*   srcIdx = (const int*)d_in[3];     // (4, 4096)
    float*       out    = (float*)d_out;           // (4, 64, 6144)

    static bool attr_done = false;
    if (!attr_done) {
        cudaFuncSetAttribute(conv_mma, cudaFuncAttributeMaxDynamicSharedMemorySize, SMEM_TOTAL);
        attr_done = true;
    }

    wprep_frag<<<(IN_DIM * 2 * 4 * 512 + 255) / 256, 256>>>(weight);
    conv_mma<<<BB * NTILES, THREADS, SMEM_TOTAL>>>(x, srcIdx, bias, out);
}

// round 12
// speedup vs baseline: 1.2766x; 1.2766x over previous
#include <cuda_runtime.h>
#include <cuda_bf16.h>
#include <cstdint>

#define BB      4
#define IN_DIM  8
#define OUT_DIM 64
#define N_WIN   64
#define N_SEQ   4096
#define N_REAL  6144

#define T_TILE  32
#define NTILES  (N_REAL / T_TILE)   // 192
#define THREADS 256

// Precomputed B fragment table (validated R8 layout): per (i, nb) 512 uint4 =
// [kc:4][slot:4][lane:32], slots = {bh0-3, bh4-7, bl0-3, bl4-7}. 128KB.
__device__ __align__(16) uint32_t g_Bf[IN_DIM * 2 * 4 * 512];

// ---------------- helpers ----------------

// pack {lo16: bf16(z0), hi16: bf16(z1)}
__device__ __forceinline__ uint32_t bfpair(float z0, float z1) {
    uint32_t r;
    asm("cvt.rn.bf16x2.f32 %0, %1, %2;" : "=r"(r) : "f"(z1), "f"(z0));
    return r;
}

__device__ __forceinline__ void mma_bf16(float* d, const uint32_t* a, uint32_t b0, uint32_t b1) {
    asm volatile(
        "mma.sync.aligned.m16n8k16.row.col.f32.bf16.bf16.f32 "
        "{%0,%1,%2,%3}, {%4,%5,%6,%7}, {%8,%9}, {%0,%1,%2,%3};"
        : "+f"(d[0]), "+f"(d[1]), "+f"(d[2]), "+f"(d[3])
        : "r"(a[0]), "r"(a[1]), "r"(a[2]), "r"(a[3]), "r"(b0), "r"(b1));
}

// ---------------- weight prep (identical to validated R8) ----------------

__global__ void wprep_frag(const float* __restrict__ w) {
    int g = blockIdx.x * 256 + threadIdx.x;     // 32768 words
    if (g >= IN_DIM * 2 * 4 * 512) return;
    int lane = g & 31;
    int j    = (g >> 5) & 15;
    int kc   = (g >> 9) & 3;
    int nb   = (g >> 11) & 1;
    int i    = (g >> 12) & 7;
    int f    = j & 7;
    int lopart = j >> 3;
    int c = f >> 1, q = f & 1;
    int o  = 32 * nb + 8 * c + (lane >> 2);
    int kk = 16 * kc + 2 * (lane & 3) + 8 * q;
    float v0 = w[(o * IN_DIM + i) * N_WIN + (63 - kk)];
    float v1 = w[(o * IN_DIM + i) * N_WIN + (62 - kk)];
    __nv_bfloat16 h0 = __float2bfloat16(v0), h1 = __float2bfloat16(v1);
    uint32_t word;
    if (!lopart) word = bfpair(__bfloat162float(h0), __bfloat162float(h1));
    else         word = bfpair(v0 - __bfloat162float(h0), v1 - __bfloat162float(h1));
    int idx = (((i * 2 + nb) * 4 + kc) * 4 + (j >> 2)) * 128 + lane * 4 + (j & 3);
    g_Bf[idx] = word;
}

// ---------------- main kernel ----------------
// SMEM: zpair_hi 8x128 u32 @0 | zpair_lo @4096 | zraw 8x128 f32 @8192 |
//       bias @12288 | outtile 64x36 f32 @12544
#define SM_ZPH  0
#define SM_ZPL  4096
#define SM_ZRAW 8192
#define SM_BIAS 12288
#define SM_OUT  12544
#define PITCHW  36
#define SMEM_TOTAL (SM_OUT + OUT_DIM * PITCHW * 4)   // 21760

__global__ __launch_bounds__(THREADS, 4)
void conv_mma(const float* __restrict__ x, const int* __restrict__ srcIdx,
              const float* __restrict__ bias, float* __restrict__ out) {
    extern __shared__ __align__(16) unsigned char smem[];
    uint32_t* zph_all = (uint32_t*)(smem + SM_ZPH);
    uint32_t* zpl_all = (uint32_t*)(smem + SM_ZPL);
    float*    zraw    = (float*)(smem + SM_ZRAW);
    float*    bias_s  = (float*)(smem + SM_BIAS);
    float*    outtile = (float*)(smem + SM_OUT);

    const int tid  = threadIdx.x;
    const int wid  = tid >> 5;
    const int lane = tid & 31;
    const int b    = blockIdx.x / NTILES;
    const int t0   = (blockIdx.x % NTILES) * T_TILE;

    if (tid < OUT_DIM) bias_s[tid] = bias[tid];
#pragma unroll
    for (int p = 0; p < 4; p++) zraw[tid + p * THREADS] = 0.f;
    __syncthreads();

    // ---- stage z window [t0-63, t0+31] (95 entries) via parallel scan ----
    {
        const int tlo = t0 - 63;
        const int4* r4 = (const int4*)(srcIdx + b * N_SEQ) + tid * 4;
        const float* xb = x + b * IN_DIM * N_SEQ;
#pragma unroll
        for (int q = 0; q < 4; q++) {
            int4 v = r4[q];
            int s0 = tid * 16 + q * 4;
            int vv[4] = {v.x, v.y, v.z, v.w};
#pragma unroll
            for (int e = 0; e < 4; e++) {
                int tl = vv[e] - tlo;
                if ((unsigned)tl < 95u) {
                    int s = s0 + e;
#pragma unroll
                    for (int i = 0; i < IN_DIM; i++)
                        zraw[i * 128 + tl] = xb[i * N_SEQ + s];
                }
            }
        }
    }
    __syncthreads();

    // ---- build hi/lo pair tables: zpair[i][k] = pack(z[k], z[k+1]) ----
#pragma unroll
    for (int p = 0; p < 4; p++) {
        int e = tid + p * THREADS;                   // 0..1023
        int k = e & 127;                             // stride 128 -> mask exact
        float z0 = zraw[e];
        float z1 = (k < 127) ? zraw[e + 1] : 0.f;
        uint32_t hp = bfpair(z0, z1);
        float h0 = __uint_as_float(hp << 16);
        float h1 = __uint_as_float(hp & 0xffff0000u);
        zph_all[e] = hp;
        zpl_all[e] = bfpair(z0 - h0, z1 - h1);
    }
    __syncthreads();

    // ---- fragment geometry: warp = (ih k-half, nb n32-half, mb m16 tile) ----
    const int mb  = wid & 1;                         // t rows [16mb, 16mb+16)
    const int nb  = (wid >> 1) & 1;                  // o half
    const int ih  = wid >> 2;                        // i in [4ih, 4ih+4)
    const int lg  = lane >> 2;
    const int lp4 = lane & 3;
    const int rA  = 16 * mb + lg;

    float acc[4][4];
#pragma unroll
    for (int c = 0; c < 4; c++)
#pragma unroll
        for (int q = 0; q < 4; q++) acc[c][q] = 0.f;

    const uint4* bf_base = (const uint4*)g_Bf + nb * 512 + lane;

    // ---- main loop: 16 steps (4 i x 4 kc), plain R8-style body ----
#pragma unroll 2
    for (int i2 = 0; i2 < 4; i2++) {
        const int i = 4 * ih + i2;
        const uint32_t* zph = zph_all + i * 128;
        const uint32_t* zpl = zpl_all + i * 128;
        const uint4*    bfi = bf_base + i * 1024;
#pragma unroll
        for (int kc = 0; kc < 4; kc++) {
            const int cb = 16 * kc + 2 * lp4;
            // Hankel A: A[r][c]=zwin[r+c] -> (row+8) and (col+8) share a word
            uint32_t w0h = zph[rA + cb], w8h = zph[rA + cb + 8], w16h = zph[rA + cb + 16];
            uint32_t w0l = zpl[rA + cb], w8l = zpl[rA + cb + 8], w16l = zpl[rA + cb + 16];
            uint32_t ah[4] = {w0h, w8h, w8h, w16h};
            uint32_t al[4] = {w0l, w8l, w8l, w16l};

            const uint4* bp = bfi + kc * 128;
            uint4 B0 = bp[0], B1 = bp[32], B2 = bp[64], B3 = bp[96];
            uint32_t bh[8] = {B0.x, B0.y, B0.z, B0.w, B1.x, B1.y, B1.z, B1.w};
            uint32_t bl[8] = {B2.x, B2.y, B2.z, B2.w, B3.x, B3.y, B3.z, B3.w};

#pragma unroll
            for (int c = 0; c < 4; c++) mma_bf16(acc[c], ah, bh[2 * c], bh[2 * c + 1]); // zhi*whi
#pragma unroll
            for (int c = 0; c < 4; c++) mma_bf16(acc[c], ah, bl[2 * c], bl[2 * c + 1]); // zhi*wlo
#pragma unroll
            for (int c = 0; c < 4; c++) mma_bf16(acc[c], al, bh[2 * c], bh[2 * c + 1]); // zlo*whi
        }
    }

    // ---- epilogue: combine k-halves in smem, add bias, transpose ----
    if (ih == 0) {
#pragma unroll
        for (int c = 0; c < 4; c++) {
            int o0 = 32 * nb + 8 * c + 2 * lp4;
            outtile[o0 * PITCHW + rA]           = acc[c][0] + bias_s[o0];
            outtile[(o0 + 1) * PITCHW + rA]     = acc[c][1] + bias_s[o0 + 1];
            outtile[o0 * PITCHW + rA + 8]       = acc[c][2] + bias_s[o0];
            outtile[(o0 + 1) * PITCHW + rA + 8] = acc[c][3] + bias_s[o0 + 1];
        }
    }
    __syncthreads();
    if (ih == 1) {
#pragma unroll
        for (int c = 0; c < 4; c++) {
            int o0 = 32 * nb + 8 * c + 2 * lp4;
            outtile[o0 * PITCHW + rA]           += acc[c][0];
            outtile[(o0 + 1) * PITCHW + rA]     += acc[c][1];
            outtile[o0 * PITCHW + rA + 8]       += acc[c][2];
            outtile[(o0 + 1) * PITCHW + rA + 8] += acc[c][3];
        }
    }
    __syncthreads();

    // ---- coalesced stores: 512 float4 quads, 2 per thread ----
#pragma unroll
    for (int r2 = 0; r2 < 2; r2++) {
        int u  = tid + r2 * THREADS;                 // 0..511
        int o  = u >> 3;
        int tq = u & 7;
        float4 v = *(float4*)(outtile + o * PITCHW + 4 * tq);
        *(float4*)(out + (b * OUT_DIM + o) * N_REAL + t0 + 4 * tq) = v;
    }
}

// ---------------- launch ----------------

extern "C" void kernel_launch(void* const* d_in, const int* in_sizes, int n_in,
                              void* d_out, int out_size) {
    const float* x      = (const float*)d_in[0];   // (4, 8, 4096)
    const float* weight = (const float*)d_in[1];   // (64, 8, 64)
    const float* bias   = (const float*)d_in[2];   // (64,)
    const int*   srcIdx = (const int*)d_in[3];     // (4, 4096)
    float*       out    = (float*)d_out;           // (4, 64, 6144)

    static bool attr_done = false;
    if (!attr_done) {
        cudaFuncSetAttribute(conv_mma, cudaFuncAttributeMaxDynamicSharedMemorySize, SMEM_TOTAL);
        attr_done = true;
    }

    wprep_frag<<<(IN_DIM * 2 * 4 * 512 + 255) / 256, 256>>>(weight);
    conv_mma<<<BB * NTILES, THREADS, SMEM_TOTAL>>>(x, srcIdx, bias, out);
}

// round 13
// speedup vs baseline: 1.5997x; 1.2531x over previous
#include <cuda_runtime.h>
#include <cuda_bf16.h>
#include <cstdint>

#define BB      4
#define IN_DIM  8
#define OUT_DIM 64
#define N_WIN   64
#define N_SEQ   4096
#define N_REAL  6144

#define T_TILE  64
#define NTILES  (N_REAL / T_TILE)   // 96
#define THREADS 256

// Precomputed B fragment table (validated R8 layout): per (i, nb) 512 uint4 =
// [kc:4][slot:4][lane:32], slots = {bh0-3, bh4-7, bl0-3, bl4-7}. 128KB.
__device__ __align__(16) uint32_t g_Bf[IN_DIM * 2 * 4 * 512];

// ---------------- helpers ----------------

// pack {lo16: bf16(z0), hi16: bf16(z1)}
__device__ __forceinline__ uint32_t bfpair(float z0, float z1) {
    uint32_t r;
    asm("cvt.rn.bf16x2.f32 %0, %1, %2;" : "=r"(r) : "f"(z1), "f"(z0));
    return r;
}

__device__ __forceinline__ void mma_bf16(float* d, const uint32_t* a, uint32_t b0, uint32_t b1) {
    asm volatile(
        "mma.sync.aligned.m16n8k16.row.col.f32.bf16.bf16.f32 "
        "{%0,%1,%2,%3}, {%4,%5,%6,%7}, {%8,%9}, {%0,%1,%2,%3};"
        : "+f"(d[0]), "+f"(d[1]), "+f"(d[2]), "+f"(d[3])
        : "r"(a[0]), "r"(a[1]), "r"(a[2]), "r"(a[3]), "r"(b0), "r"(b1));
}

// ---------------- weight prep (identical to validated R8) ----------------

__global__ void wprep_frag(const float* __restrict__ w) {
    int g = blockIdx.x * 256 + threadIdx.x;     // 32768 words
    if (g >= IN_DIM * 2 * 4 * 512) return;
    int lane = g & 31;
    int j    = (g >> 5) & 15;
    int kc   = (g >> 9) & 3;
    int nb   = (g >> 11) & 1;
    int i    = (g >> 12) & 7;
    int f    = j & 7;
    int lopart = j >> 3;
    int c = f >> 1, q = f & 1;
    int o  = 32 * nb + 8 * c + (lane >> 2);
    int kk = 16 * kc + 2 * (lane & 3) + 8 * q;
    float v0 = w[(o * IN_DIM + i) * N_WIN + (63 - kk)];
    float v1 = w[(o * IN_DIM + i) * N_WIN + (62 - kk)];
    __nv_bfloat16 h0 = __float2bfloat16(v0), h1 = __float2bfloat16(v1);
    uint32_t word;
    if (!lopart) word = bfpair(__bfloat162float(h0), __bfloat162float(h1));
    else         word = bfpair(v0 - __bfloat162float(h0), v1 - __bfloat162float(h1));
    int idx = (((i * 2 + nb) * 4 + kc) * 4 + (j >> 2)) * 128 + lane * 4 + (j & 3);
    g_Bf[idx] = word;
}

// ---------------- main kernel ----------------
// SMEM: zpair_hi 8x128 u32 @0 | zpair_lo @4096 | zraw 8x128 f32 @8192 |
//       bias @12288 | outtile 64x68 f32 @12544
#define SM_ZPH  0
#define SM_ZPL  4096
#define SM_ZRAW 8192
#define SM_BIAS 12288
#define SM_OUT  12544
#define PITCHW  68
#define SMEM_TOTAL (SM_OUT + OUT_DIM * PITCHW * 4)   // 29952

__global__ __launch_bounds__(THREADS, 3)
void conv_mma(const float* __restrict__ x, const int* __restrict__ srcIdx,
              const float* __restrict__ bias, float* __restrict__ out) {
    extern __shared__ __align__(16) unsigned char smem[];
    uint32_t* zph_all = (uint32_t*)(smem + SM_ZPH);
    uint32_t* zpl_all = (uint32_t*)(smem + SM_ZPL);
    float*    zraw    = (float*)(smem + SM_ZRAW);
    float*    bias_s  = (float*)(smem + SM_BIAS);
    float*    outtile = (float*)(smem + SM_OUT);

    const int tid  = threadIdx.x;
    const int wid  = tid >> 5;
    const int lane = tid & 31;
    const int b    = blockIdx.x / NTILES;
    const int t0   = (blockIdx.x % NTILES) * T_TILE;

    if (tid < OUT_DIM) bias_s[tid] = bias[tid];
#pragma unroll
    for (int p = 0; p < 4; p++) zraw[tid + p * THREADS] = 0.f;
    __syncthreads();

    // ---- stage z window [t0-63, t0+63] (127 entries) via parallel scan ----
    {
        const int tlo = t0 - 63;
        const int4* r4 = (const int4*)(srcIdx + b * N_SEQ) + tid * 4;
        const float* xb = x + b * IN_DIM * N_SEQ;
#pragma unroll
        for (int q = 0; q < 4; q++) {
            int4 v = r4[q];
            int s0 = tid * 16 + q * 4;
            int vv[4] = {v.x, v.y, v.z, v.w};
#pragma unroll
            for (int e = 0; e < 4; e++) {
                int tl = vv[e] - tlo;
                if ((unsigned)tl < 127u) {
                    int s = s0 + e;
#pragma unroll
                    for (int i = 0; i < IN_DIM; i++)
                        zraw[i * 128 + tl] = xb[i * N_SEQ + s];
                }
            }
        }
    }
    __syncthreads();

    // ---- build hi/lo pair tables: zpair[i][k] = pack(z[k], z[k+1]) ----
#pragma unroll
    for (int p = 0; p < 4; p++) {
        int e = tid + p * THREADS;                   // 0..1023
        int k = e & 127;                             // stride 128 -> mask exact
        float z0 = zraw[e];
        float z1 = (k < 127) ? zraw[e + 1] : 0.f;
        uint32_t hp = bfpair(z0, z1);
        float h0 = __uint_as_float(hp << 16);
        float h1 = __uint_as_float(hp & 0xffff0000u);
        zph_all[e] = hp;
        zpl_all[e] = bfpair(z0 - h0, z1 - h1);
    }
    __syncthreads();

    // ---- fragment geometry: warp = (mb2 m32-tile, nb n32-half, ih k-half) ----
    const int mb2 = wid & 1;                         // t rows [32mb2, 32mb2+32)
    const int nb  = (wid >> 1) & 1;                  // o half
    const int ih  = wid >> 2;                        // i in [4ih, 4ih+4)
    const int lg  = lane >> 2;
    const int lp4 = lane & 3;
    const int rA  = 32 * mb2 + lg;

    float acc[2][4][4];                              // [m16 subtile][n8 group][frag]
#pragma unroll
    for (int mt = 0; mt < 2; mt++)
#pragma unroll
        for (int c = 0; c < 4; c++)
#pragma unroll
            for (int q = 0; q < 4; q++) acc[mt][c][q] = 0.f;

    const uint4* bf_base = (const uint4*)g_Bf + nb * 512 + lane;

    // ---- main loop: 16 steps (4 i x 4 kc), m32n32 per warp ----
#pragma unroll 2
    for (int i2 = 0; i2 < 4; i2++) {
        const int i = 4 * ih + i2;
        const uint32_t* zph = zph_all + i * 128;
        const uint32_t* zpl = zpl_all + i * 128;
        const uint4*    bfi = bf_base + i * 1024;
#pragma unroll
        for (int kc = 0; kc < 4; kc++) {
            const int base = rA + 16 * kc + 2 * lp4;
            // Hankel: 5 distinct hi words + 5 lo cover both m16 tiles
            uint32_t h0 = zph[base],      h1 = zph[base + 8],  h2 = zph[base + 16],
                     h3 = zph[base + 24], h4 = zph[base + 32];
            uint32_t l0 = zpl[base],      l1 = zpl[base + 8],  l2 = zpl[base + 16],
                     l3 = zpl[base + 24], l4 = zpl[base + 32];
            uint32_t ah0[4] = {h0, h1, h1, h2};      // m16 tile 0 (rows rA..)
            uint32_t ah1[4] = {h2, h3, h3, h4};      // m16 tile 1 (rows rA+16..)
            uint32_t al0[4] = {l0, l1, l1, l2};
            uint32_t al1[4] = {l2, l3, l3, l4};

            const uint4* bp = bfi + kc * 128;
            uint4 B0 = bp[0], B1 = bp[32], B2 = bp[64], B3 = bp[96];
            uint32_t bh[8] = {B0.x, B0.y, B0.z, B0.w, B1.x, B1.y, B1.z, B1.w};
            uint32_t bl[8] = {B2.x, B2.y, B2.z, B2.w, B3.x, B3.y, B3.z, B3.w};

            // term-outer ordering: same-acc reuse distance = 8
#pragma unroll
            for (int c = 0; c < 4; c++) mma_bf16(acc[0][c], ah0, bh[2 * c], bh[2 * c + 1]);
#pragma unroll
            for (int c = 0; c < 4; c++) mma_bf16(acc[1][c], ah1, bh[2 * c], bh[2 * c + 1]);
#pragma unroll
            for (int c = 0; c < 4; c++) mma_bf16(acc[0][c], ah0, bl[2 * c], bl[2 * c + 1]);
#pragma unroll
            for (int c = 0; c < 4; c++) mma_bf16(acc[1][c], ah1, bl[2 * c], bl[2 * c + 1]);
#pragma unroll
            for (int c = 0; c < 4; c++) mma_bf16(acc[0][c], al0, bh[2 * c], bh[2 * c + 1]);
#pragma unroll
            for (int c = 0; c < 4; c++) mma_bf16(acc[1][c], al1, bh[2 * c], bh[2 * c + 1]);
        }
    }

    // ---- epilogue: combine k-halves in smem, add bias, transpose ----
    if (ih == 0) {
#pragma unroll
        for (int mt = 0; mt < 2; mt++)
#pragma unroll
            for (int c = 0; c < 4; c++) {
                int o0 = 32 * nb + 8 * c + 2 * lp4;
                int tl = rA + 16 * mt;
                outtile[o0 * PITCHW + tl]           = acc[mt][c][0] + bias_s[o0];
                outtile[(o0 + 1) * PITCHW + tl]     = acc[mt][c][1] + bias_s[o0 + 1];
                outtile[o0 * PITCHW + tl + 8]       = acc[mt][c][2] + bias_s[o0];
                outtile[(o0 + 1) * PITCHW + tl + 8] = acc[mt][c][3] + bias_s[o0 + 1];
            }
    }
    __syncthreads();
    if (ih == 1) {
#pragma unroll
        for (int mt = 0; mt < 2; mt++)
#pragma unroll
            for (int c = 0; c < 4; c++) {
                int o0 = 32 * nb + 8 * c + 2 * lp4;
                int tl = rA + 16 * mt;
                outtile[o0 * PITCHW + tl]           += acc[mt][c][0];
                outtile[(o0 + 1) * PITCHW + tl]     += acc[mt][c][1];
                outtile[o0 * PITCHW + tl + 8]       += acc[mt][c][2];
                outtile[(o0 + 1) * PITCHW + tl + 8] += acc[mt][c][3];
            }
    }
    __syncthreads();

    // ---- coalesced STG.128: 1024 float4 quads, 4 per thread ----
#pragma unroll
    for (int r2 = 0; r2 < 4; r2++) {
        int u  = tid + r2 * THREADS;                 // 0..1023
        int o  = u >> 4;
        int tq = u & 15;
        float4 v = *(float4*)(outtile + o * PITCHW + 4 * tq);
        *(float4*)(out + (b * OUT_DIM + o) * N_REAL + t0 + 4 * tq) = v;
    }
}

// ---------------- launch ----------------

extern "C" void kernel_launch(void* const* d_in, const int* in_sizes, int n_in,
                              void* d_out, int out_size) {
    const float* x      = (const float*)d_in[0];   // (4, 8, 4096)
    const float* weight = (const float*)d_in[1];   // (64, 8, 64)
    const float* bias   = (const float*)d_in[2];   // (64,)
    const int*   srcIdx = (const int*)d_in[3];     // (4, 4096)
    float*       out    = (float*)d_out;           // (4, 64, 6144)

    static bool attr_done = false;
    if (!attr_done) {
        cudaFuncSetAttribute(conv_mma, cudaFuncAttributeMaxDynamicSharedMemorySize, SMEM_TOTAL);
        attr_done = true;
    }

    wprep_frag<<<(IN_DIM * 2 * 4 * 512 + 255) / 256, 256>>>(weight);
    conv_mma<<<BB * NTILES, THREADS, SMEM_TOTAL>>>(x, srcIdx, bias, out);
}

// round 14
// speedup vs baseline: 1.7756x; 1.1099x over previous
#include <cuda_runtime.h>
#include <cuda_bf16.h>
#include <cstdint>

#define BB      4
#define IN_DIM  8
#define OUT_DIM 64
#define N_WIN   64
#define N_SEQ   4096
#define N_REAL  6144

#define T_TILE  64
#define NTILES  (N_REAL / T_TILE)   // 96
#define THREADS 256

// Precomputed tf32 B fragment table: per (i,nb,s) 2 uint4-slots per lane.
// word index g = i<<12 | nb<<11 | s<<8 | sl<<7 | lane<<2 | wd. 128KB.
__device__ __align__(16) uint32_t g_Bf[IN_DIM * 2 * 8 * 2 * 32 * 4];

// ---------------- helpers ----------------

__device__ __forceinline__ uint32_t tf32r(float v) {
    uint32_t r;
    asm("cvt.rna.tf32.f32 %0, %1;" : "=r"(r) : "f"(v));
    return r;
}

__device__ __forceinline__ void mma_tf32(float* d, const uint32_t* a, uint32_t b0, uint32_t b1) {
    asm volatile(
        "mma.sync.aligned.m16n8k8.row.col.f32.tf32.tf32.f32 "
        "{%0,%1,%2,%3}, {%4,%5,%6,%7}, {%8,%9}, {%0,%1,%2,%3};"
        : "+f"(d[0]), "+f"(d[1]), "+f"(d[2]), "+f"(d[3])
        : "r"(a[0]), "r"(a[1]), "r"(a[2]), "r"(a[3]), "r"(b0), "r"(b1));
}

// ---------------- weight prep: per-lane tf32 B fragments, lag flipped ----------------
// B[k][o] = W[o][i][63-k].  m16n8k8 col-B fragment, n8 group c, reg q:
//   word of lane l = B[8s + l%4 + 4q][32nb + 8c + l/4], stored rna-rounded to tf32.

__global__ void wprep_frag(const float* __restrict__ w) {
    int g = blockIdx.x * 256 + threadIdx.x;     // 32768 words
    if (g >= IN_DIM * 2 * 8 * 2 * 32 * 4) return;
    int wd   = g & 3;
    int lane = (g >> 2) & 31;
    int sl   = (g >> 7) & 1;
    int s    = (g >> 8) & 7;
    int nb   = (g >> 11) & 1;
    int i    = (g >> 12) & 7;
    int f = 4 * sl + wd;                        // fragment word 0..7
    int c = f >> 1, q = f & 1;                  // n8 group, reg index
    int o  = 32 * nb + 8 * c + (lane >> 2);
    int kk = 8 * s + (lane & 3) + 4 * q;
    g_Bf[g] = tf32r(w[(o * IN_DIM + i) * N_WIN + (63 - kk)]);
}

// ---------------- main kernel ----------------
// SMEM: zraw 8x128 f32 @0 | bias @4096 | outtile 64x68 f32 @4352
#define SM_ZRAW 0
#define SM_BIAS 4096
#define SM_OUT  4352
#define PITCHW  68
#define SMEM_TOTAL (SM_OUT + OUT_DIM * PITCHW * 4)   // 21760

__global__ __launch_bounds__(THREADS, 3)
void conv_mma(const float* __restrict__ x, const int* __restrict__ srcIdx,
              const float* __restrict__ bias, float* __restrict__ out) {
    extern __shared__ __align__(16) unsigned char smem[];
    float* zraw    = (float*)(smem + SM_ZRAW);
    float* bias_s  = (float*)(smem + SM_BIAS);
    float* outtile = (float*)(smem + SM_OUT);

    const int tid  = threadIdx.x;
    const int wid  = tid >> 5;
    const int lane = tid & 31;
    const int b    = blockIdx.x / NTILES;
    const int t0   = (blockIdx.x % NTILES) * T_TILE;

    if (tid < OUT_DIM) bias_s[tid] = bias[tid];
#pragma unroll
    for (int p = 0; p < 4; p++) zraw[tid + p * THREADS] = 0.f;
    __syncthreads();

    // ---- stage z window [t0-63, t0+63] (127 entries) via parallel scan ----
    {
        const int tlo = t0 - 63;
        const int4* r4 = (const int4*)(srcIdx + b * N_SEQ) + tid * 4;
        const float* xb = x + b * IN_DIM * N_SEQ;
#pragma unroll
        for (int q = 0; q < 4; q++) {
            int4 v = r4[q];
            int s0 = tid * 16 + q * 4;
            int vv[4] = {v.x, v.y, v.z, v.w};
#pragma unroll
            for (int e = 0; e < 4; e++) {
                int tl = vv[e] - tlo;
                if ((unsigned)tl < 127u) {
                    int s = s0 + e;
#pragma unroll
                    for (int i = 0; i < IN_DIM; i++)
                        zraw[i * 128 + tl] = xb[i * N_SEQ + s];
                }
            }
        }
    }
    __syncthreads();

    // ---- round A operand to tf32 (rna) so HW sees exact tf32 values ----
#pragma unroll
    for (int p = 0; p < 4; p++) {
        int e = tid + p * THREADS;
        zraw[e] = __uint_as_float(tf32r(zraw[e]));
    }
    __syncthreads();

    // ---- fragment geometry: warp = (mb2 m32-tile, nb n32-half, ih k-half) ----
    const int mb2 = wid & 1;                         // t rows [32mb2, 32mb2+32)
    const int nb  = (wid >> 1) & 1;                  // o half
    const int ih  = wid >> 2;                        // i in [4ih, 4ih+4)
    const int lg  = lane >> 2;
    const int lp4 = lane & 3;
    const int rA  = 32 * mb2 + lg;

    float acc[2][4][4];                              // [m16 subtile][n8 group][frag]
#pragma unroll
    for (int mt = 0; mt < 2; mt++)
#pragma unroll
        for (int c = 0; c < 4; c++)
#pragma unroll
            for (int q = 0; q < 4; q++) acc[mt][c][q] = 0.f;

    // ---- main loop: 4 i x 8 k8-steps, Hankel register sliding window ----
#pragma unroll 2
    for (int i2 = 0; i2 < 4; i2++) {
        const int i = 4 * ih + i2;
        const float* zi  = zraw + i * 128 + rA + lp4;
        const uint4* bfi = (const uint4*)g_Bf + (i * 2 + nb) * 512 + lane;

        // window: win[j] = z bits at element offset 8s + 4j (init s=0)
        uint32_t win[8];
#pragma unroll
        for (int j = 0; j < 8; j++) win[j] = __float_as_uint(zi[4 * j]);

#pragma unroll
        for (int s = 0; s < 8; s++) {
            const uint4* bp = bfi + s * 64;
            uint4 B0 = bp[0], B1 = bp[32];
            uint32_t bb[8] = {B0.x, B0.y, B0.z, B0.w, B1.x, B1.y, B1.z, B1.w};

            // m16n8k8 A frag: {A[lg][lp4], A[lg+8][lp4], A[lg][lp4+4], A[lg+8][lp4+4]}
            uint32_t a0[4] = {win[0], win[2], win[1], win[3]};   // rows rA..rA+15
            uint32_t a1[4] = {win[4], win[6], win[5], win[7]};   // rows rA+16..rA+31

#pragma unroll
            for (int c = 0; c < 4; c++) mma_tf32(acc[0][c], a0, bb[2 * c], bb[2 * c + 1]);
#pragma unroll
            for (int c = 0; c < 4; c++) mma_tf32(acc[1][c], a1, bb[2 * c], bb[2 * c + 1]);

            if (s < 7) {
                // slide window by one k8-step (8 elements): reuse 6, load 2
#pragma unroll
                for (int j = 0; j < 6; j++) win[j] = win[j + 2];
                win[6] = __float_as_uint(zi[8 * s + 32]);
                win[7] = __float_as_uint(zi[8 * s + 36]);
            }
        }
    }

    // ---- epilogue: combine k-halves in smem, add bias, transpose ----
    if (ih == 0) {
#pragma unroll
        for (int mt = 0; mt < 2; mt++)
#pragma unroll
            for (int c = 0; c < 4; c++) {
                int o0 = 32 * nb + 8 * c + 2 * lp4;
                int tl = rA + 16 * mt;
                outtile[o0 * PITCHW + tl]           = acc[mt][c][0] + bias_s[o0];
                outtile[(o0 + 1) * PITCHW + tl]     = acc[mt][c][1] + bias_s[o0 + 1];
                outtile[o0 * PITCHW + tl + 8]       = acc[mt][c][2] + bias_s[o0];
                outtile[(o0 + 1) * PITCHW + tl + 8] = acc[mt][c][3] + bias_s[o0 + 1];
            }
    }
    __syncthreads();
    if (ih == 1) {
#pragma unroll
        for (int mt = 0; mt < 2; mt++)
#pragma unroll
            for (int c = 0; c < 4; c++) {
                int o0 = 32 * nb + 8 * c + 2 * lp4;
                int tl = rA + 16 * mt;
                outtile[o0 * PITCHW + tl]           += acc[mt][c][0];
                outtile[(o0 + 1) * PITCHW + tl]     += acc[mt][c][1];
                outtile[o0 * PITCHW + tl + 8]       += acc[mt][c][2];
                outtile[(o0 + 1) * PITCHW + tl + 8] += acc[mt][c][3];
            }
    }
    __syncthreads();

    // ---- coalesced STG.128: 1024 float4 quads, 4 per thread ----
#pragma unroll
    for (int r2 = 0; r2 < 4; r2++) {
        int u  = tid + r2 * THREADS;                 // 0..1023
        int o  = u >> 4;
        int tq = u & 15;
        float4 v = *(float4*)(outtile + o * PITCHW + 4 * tq);
        *(float4*)(out + (b * OUT_DIM + o) * N_REAL + t0 + 4 * tq) = v;
    }
}

// ---------------- launch ----------------

extern "C" void kernel_launch(void* const* d_in, const int* in_sizes, int n_in,
                              void* d_out, int out_size) {
    const float* x      = (const float*)d_in[0];   // (4, 8, 4096)
    const float* weight = (const float*)d_in[1];   // (64, 8, 64)
    const float* bias   = (const float*)d_in[2];   // (64,)
    const int*   srcIdx = (const int*)d_in[3];     // (4, 4096)
    float*       out    = (float*)d_out;           // (4, 64, 6144)

    static bool attr_done = false;
    if (!attr_done) {
        cudaFuncSetAttribute(conv_mma, cudaFuncAttributeMaxDynamicSharedMemorySize, SMEM_TOTAL);
        attr_done = true;
    }

    wprep_frag<<<(IN_DIM * 2 * 8 * 2 * 32 * 4 + 255) / 256, 256>>>(weight);
    conv_mma<<<BB * NTILES, THREADS, SMEM_TOTAL>>>(x, srcIdx, bias, out);
}